// round 4
// baseline (speedup 1.0000x reference)
#include <cuda_runtime.h>
#include <cstdint>

// TopK keep: zero all but the K=512 largest entries per 4096-wide row.
// x: f32[4,4096,4096] -> 16384 rows. One CTA (512 threads) per row,
// 8 elements per thread, keys register-resident throughout.
//
// 3-level radix select (8 + 12 + 12 bits) on monotonic uint keys.
// Exact tie handling: threshold T + stable rank keeps lowest-index ==T
// elements, matching jax.lax.top_k bit-exactly.

#define D_DIM   4096
#define K_KEEP  512
#define NT      512
#define PT      8    // elements per thread (contiguous: tid*8 .. tid*8+7)
#define NW      16   // warps per CTA

__device__ __forceinline__ unsigned f2k(float f) {
    unsigned u = __float_as_uint(f);
    return u ^ ((unsigned)((int)u >> 31) | 0x80000000u);
}
__device__ __forceinline__ float k2f(unsigned k) {
    return __uint_as_float(k ^ ((unsigned)((int)(~k) >> 31) | 0x80000000u));
}

__global__ __launch_bounds__(NT, 3)
void topk_keep_kernel(const float* __restrict__ x, float* __restrict__ out)
{
    __shared__ __align__(16) unsigned histA[NW * 256];  // per-warp 256-bin
    __shared__ __align__(16) unsigned histB[4096];
    __shared__ __align__(16) unsigned histC[4096];
    __shared__ unsigned wsum[NW];
    __shared__ unsigned selb, selk;

    const int tid  = threadIdx.x;
    const int lane = tid & 31;
    const int warp = tid >> 5;
    const size_t row = (size_t)blockIdx.x * D_DIM;

    // ---------------- load + convert: 8 keys in registers ----------------
    const float4* xr = reinterpret_cast<const float4*>(x + row) + tid * 2;
    unsigned k0[PT];
    {
        float4 v0 = xr[0], v1 = xr[1];
        k0[0]=f2k(v0.x); k0[1]=f2k(v0.y); k0[2]=f2k(v0.z); k0[3]=f2k(v0.w);
        k0[4]=f2k(v1.x); k0[5]=f2k(v1.y); k0[6]=f2k(v1.z); k0[7]=f2k(v1.w);
    }

    // ---------------- zero all histograms once ----------------
    const uint4 z4 = make_uint4(0u, 0u, 0u, 0u);
    {
        uint4* a = reinterpret_cast<uint4*>(histA);   // 1024 uint4
        uint4* b = reinterpret_cast<uint4*>(histB);   // 1024 uint4
        uint4* c = reinterpret_cast<uint4*>(histC);   // 1024 uint4
        a[tid] = z4;  a[tid + 512] = z4;
        b[tid] = z4;  b[tid + 512] = z4;
        c[tid] = z4;  c[tid + 512] = z4;
    }
    __syncthreads();                                            // S1

    // ---------------- level A: digit = key >> 24 (per-warp hist + dedup) ----
    {
        unsigned* myh = histA + warp * 256;
#pragma unroll
        for (int i = 0; i < PT; ++i) {
            unsigned d = k0[i] >> 24;
            unsigned m = __match_any_sync(0xffffffffu, d);
            if ((m & ((1u << lane) - 1u)) == 0u)
                atomicAdd(&myh[d], (unsigned)__popc(m));
        }
    }
    __syncthreads();                                            // S2

    unsigned kth = K_KEEP;
    unsigned b1;
    {
        unsigned cnt = 0, s = 0;
        if (tid < 256) {
#pragma unroll
            for (int w = 0; w < NW; ++w) cnt += histA[w * 256 + tid];
        }
        s = cnt;                                   // in-warp suffix scan
#pragma unroll
        for (int o = 1; o < 32; o <<= 1) {
            unsigned v = __shfl_down_sync(0xffffffffu, s, o);
            if (lane + o < 32) s += v;
        }
        if (lane == 0 && warp < 8) wsum[warp] = s;
        __syncthreads();                                        // S3
        if (tid < 256) {
            unsigned addh = 0;
#pragma unroll
            for (int w = 0; w < 8; ++w) if (w > warp) addh += wsum[w];
            unsigned Sincl = s + addh;             // count(digit >= tid)
            if (Sincl >= kth && Sincl - cnt < kth) {
                selb = (unsigned)tid;
                selk = kth - (Sincl - cnt);
            }
        }
        __syncthreads();                                        // S4
        b1  = selb;
        kth = selk;
    }

    // ---------------- level B: digit = (key >> 12) & 0xFFF ----------------
#pragma unroll
    for (int i = 0; i < PT; ++i) {
        unsigned k = k0[i];
        if ((k >> 24) == b1)
            atomicAdd(&histB[(k >> 12) & 0xFFFu], 1u);
    }
    __syncthreads();                                            // S5

    unsigned b2;
    {
        const uint4* hv = reinterpret_cast<const uint4*>(histB) + tid * 2;
        uint4 c0 = hv[0], c1 = hv[1];
        unsigned ct = c0.x+c0.y+c0.z+c0.w + c1.x+c1.y+c1.z+c1.w;
        unsigned s = ct;
#pragma unroll
        for (int o = 1; o < 32; o <<= 1) {
            unsigned v = __shfl_down_sync(0xffffffffu, s, o);
            if (lane + o < 32) s += v;
        }
        if (lane == 0) wsum[warp] = s;
        __syncthreads();                                        // S6
        unsigned addh = 0;
#pragma unroll
        for (int w = 0; w < NW; ++w) if (w > warp) addh += wsum[w];
        unsigned beyond = (s - ct) + addh;         // digits above my 8 bins
        if (beyond < kth && beyond + ct >= kth) {
            unsigned carr[8] = {c0.x,c0.y,c0.z,c0.w, c1.x,c1.y,c1.z,c1.w};
            unsigned rb = beyond;
#pragma unroll
            for (int j = 7; j >= 0; --j) {
                unsigned c = carr[j];
                if (rb < kth && rb + c >= kth) { selb = (unsigned)(tid * 8 + j); selk = kth - rb; }
                rb += c;
            }
        }
        __syncthreads();                                        // S7
        b2  = selb;
        kth = selk;
    }

    // ---------------- level C: digit = key & 0xFFF ----------------
    {
        const unsigned prefB = (b1 << 12) | b2;
#pragma unroll
        for (int i = 0; i < PT; ++i) {
            unsigned k = k0[i];
            if ((k >> 12) == prefB)
                atomicAdd(&histC[k & 0xFFFu], 1u);
        }
    }
    __syncthreads();                                            // S8

    unsigned b3;
    {
        const uint4* hv = reinterpret_cast<const uint4*>(histC) + tid * 2;
        uint4 c0 = hv[0], c1 = hv[1];
        unsigned ct = c0.x+c0.y+c0.z+c0.w + c1.x+c1.y+c1.z+c1.w;
        unsigned s = ct;
#pragma unroll
        for (int o = 1; o < 32; o <<= 1) {
            unsigned v = __shfl_down_sync(0xffffffffu, s, o);
            if (lane + o < 32) s += v;
        }
        if (lane == 0) wsum[warp] = s;
        __syncthreads();                                        // S9
        unsigned addh = 0;
#pragma unroll
        for (int w = 0; w < NW; ++w) if (w > warp) addh += wsum[w];
        unsigned beyond = (s - ct) + addh;
        if (beyond < kth && beyond + ct >= kth) {
            unsigned carr[8] = {c0.x,c0.y,c0.z,c0.w, c1.x,c1.y,c1.z,c1.w};
            unsigned rb = beyond;
#pragma unroll
            for (int j = 7; j >= 0; --j) {
                unsigned c = carr[j];
                if (rb < kth && rb + c >= kth) { selb = (unsigned)(tid * 8 + j); selk = kth - rb; }
                rb += c;
            }
        }
        __syncthreads();                                        // S10
        b3  = selb;
        kth = selk;
        __syncthreads();   // protect wsum before rank scan     // S11
    }

    const unsigned T    = (b1 << 24) | (b2 << 12) | b3;  // exact K-th largest key
    const unsigned need = kth;                           // # of ==T kept (lowest index)

    // ---------------- stable rank among ==T elements ----------------
    unsigned ceq = 0;
#pragma unroll
    for (int i = 0; i < PT; ++i) ceq += (k0[i] == T) ? 1u : 0u;
    unsigned p = ceq;
#pragma unroll
    for (int o = 1; o < 32; o <<= 1) {
        unsigned v = __shfl_up_sync(0xffffffffu, p, o);
        if (lane >= o) p += v;
    }
    if (lane == 31) wsum[warp] = p;
    __syncthreads();                                            // S12
    unsigned woff = 0;
#pragma unroll
    for (int w = 0; w < NW; ++w) if (w < warp) woff += wsum[w];
    unsigned rank = woff + p - ceq;   // exclusive prefix of equals, index order

    // ---------------- emit ----------------
    float4* outr = reinterpret_cast<float4*>(out + row) + tid * 2;
#pragma unroll
    for (int j = 0; j < 2; ++j) {
        float r[4];
#pragma unroll
        for (int c = 0; c < 4; ++c) {
            unsigned k = k0[j * 4 + c];
            bool eq = (k == T);
            bool keep = (k > T) || (eq && (rank < need));
            r[c] = keep ? k2f(k) : 0.0f;
            rank += eq ? 1u : 0u;
        }
        outr[j] = make_float4(r[0], r[1], r[2], r[3]);
    }
}

extern "C" void kernel_launch(void* const* d_in, const int* in_sizes, int n_in,
                              void* d_out, int out_size) {
    const float* x = (const float*)d_in[0];
    float* out = (float*)d_out;
    int rows = out_size / D_DIM;   // 16384
    topk_keep_kernel<<<rows, NT>>>(x, out);
}

// round 5
// speedup vs baseline: 1.0506x; 1.0506x over previous
#include <cuda_runtime.h>
#include <cstdint>

// TopK keep: zero all but the K=512 largest entries per 4096-wide row.
// x: f32[4,4096,4096] -> 16384 rows. One CTA (256 threads) per row,
// 16 elements/thread, keys register-resident.
//
// 3-level radix select (8 + 12 + 12 bits) on monotonic uint keys.
// One shared 4096-bin histogram reused for levels B and C (re-zeroed once)
// to keep smem at ~24KB -> 6 CTAs/SM. Scans accumulate bin sums without
// keeping all 16 bins live (winner thread reloads from smem), cutting
// register pressure. Exact ties: lowest index first (jax.lax.top_k).

#define D_DIM   4096
#define K_KEEP  512
#define NT      256
#define PT      16
#define NW      8

__device__ __forceinline__ unsigned f2k(float f) {
    unsigned u = __float_as_uint(f);
    return u ^ ((unsigned)((int)u >> 31) | 0x80000000u);
}
__device__ __forceinline__ float k2f(unsigned k) {
    return __uint_as_float(k ^ ((unsigned)((int)(~k) >> 31) | 0x80000000u));
}

__global__ __launch_bounds__(NT, 6)
void topk_keep_kernel(const float* __restrict__ x, float* __restrict__ out)
{
    __shared__ __align__(16) unsigned histA[NW * 256];  // per-warp 256-bin (8KB)
    __shared__ __align__(16) unsigned hist[4096];       // shared by levels B & C (16KB)
    __shared__ unsigned wsum[NW];
    __shared__ unsigned selb, selk;

    const int tid  = threadIdx.x;
    const int lane = tid & 31;
    const int warp = tid >> 5;
    const size_t row = (size_t)blockIdx.x * D_DIM;

    // ---------------- load + convert: 16 keys in registers ----------------
    const float4* xr = reinterpret_cast<const float4*>(x + row) + tid * 4;
    unsigned k0[PT];
    {
        float4 v0 = xr[0], v1 = xr[1], v2 = xr[2], v3 = xr[3];
        k0[0]=f2k(v0.x);  k0[1]=f2k(v0.y);  k0[2]=f2k(v0.z);  k0[3]=f2k(v0.w);
        k0[4]=f2k(v1.x);  k0[5]=f2k(v1.y);  k0[6]=f2k(v1.z);  k0[7]=f2k(v1.w);
        k0[8]=f2k(v2.x);  k0[9]=f2k(v2.y);  k0[10]=f2k(v2.z); k0[11]=f2k(v2.w);
        k0[12]=f2k(v3.x); k0[13]=f2k(v3.y); k0[14]=f2k(v3.z); k0[15]=f2k(v3.w);
    }

    // ---------------- zero histograms ----------------
    const uint4 z4 = make_uint4(0u, 0u, 0u, 0u);
    {
        uint4* a = reinterpret_cast<uint4*>(histA);  // 512 uint4
        uint4* h = reinterpret_cast<uint4*>(hist);   // 1024 uint4
        a[tid] = z4;  a[tid + 256] = z4;
        h[tid] = z4;  h[tid + 256] = z4;  h[tid + 512] = z4;  h[tid + 768] = z4;
    }
    __syncthreads();                                           // S1

    // ---------------- level A: digit = key >> 24 ----------------
    {
        unsigned* myh = histA + warp * 256;
#pragma unroll
        for (int i = 0; i < PT; ++i) {
            unsigned d = k0[i] >> 24;
            unsigned m = __match_any_sync(0xffffffffu, d);
            if ((m & ((1u << lane) - 1u)) == 0u)
                atomicAdd(&myh[d], (unsigned)__popc(m));
        }
    }
    __syncthreads();                                           // S2

    unsigned kth = K_KEEP;
    unsigned b1;
    {
        unsigned cnt = 0;
#pragma unroll
        for (int w = 0; w < NW; ++w) cnt += histA[w * 256 + tid];
        unsigned s = cnt;                       // in-warp suffix scan
#pragma unroll
        for (int o = 1; o < 32; o <<= 1) {
            unsigned v = __shfl_down_sync(0xffffffffu, s, o);
            if (lane + o < 32) s += v;
        }
        if (lane == 0) wsum[warp] = s;
        __syncthreads();                                       // S3
        unsigned addh = 0;
#pragma unroll
        for (int w = 0; w < NW; ++w) if (w > warp) addh += wsum[w];
        unsigned Sincl = s + addh;              // count(digit >= tid)
        if (Sincl >= kth && Sincl - cnt < kth) {
            selb = (unsigned)tid;
            selk = kth - (Sincl - cnt);
        }
        __syncthreads();                                       // S4
        b1  = selb;
        kth = selk;
    }

    // ---------------- level B: digit = (key >> 12) & 0xFFF ----------------
#pragma unroll
    for (int i = 0; i < PT; ++i) {
        unsigned k = k0[i];
        if ((k >> 24) == b1)
            atomicAdd(&hist[(k >> 12) & 0xFFFu], 1u);
    }
    __syncthreads();                                           // S5

    unsigned b2;
    {
        // accumulate my 16 bins without keeping them live
        unsigned ct = 0;
        {
            const uint4* hv = reinterpret_cast<const uint4*>(hist) + tid * 4;
#pragma unroll
            for (int q = 0; q < 4; ++q) {
                uint4 c = hv[q];
                ct += c.x + c.y + c.z + c.w;
            }
        }
        unsigned s = ct;
#pragma unroll
        for (int o = 1; o < 32; o <<= 1) {
            unsigned v = __shfl_down_sync(0xffffffffu, s, o);
            if (lane + o < 32) s += v;
        }
        if (lane == 0) wsum[warp] = s;
        __syncthreads();                                       // S6
        unsigned addh = 0;
#pragma unroll
        for (int w = 0; w < NW; ++w) if (w > warp) addh += wsum[w];
        unsigned beyond = (s - ct) + addh;      // count above my 16-bin chunk
        if (beyond < kth && beyond + ct >= kth) {
            unsigned rb = beyond;               // winner: reload bins from smem
            for (int j = 15; j >= 0; --j) {
                unsigned c = hist[tid * 16 + j];
                if (rb < kth && rb + c >= kth) { selb = (unsigned)(tid * 16 + j); selk = kth - rb; }
                rb += c;
            }
        }
        __syncthreads();                                       // S7
        b2  = selb;
        kth = selk;
    }

    // ---------------- re-zero shared hist for level C ----------------
    {
        uint4* h = reinterpret_cast<uint4*>(hist);
        h[tid] = z4;  h[tid + 256] = z4;  h[tid + 512] = z4;  h[tid + 768] = z4;
    }
    __syncthreads();                                           // S8

    // ---------------- level C: digit = key & 0xFFF ----------------
    {
        const unsigned prefB = (b1 << 12) | b2;
#pragma unroll
        for (int i = 0; i < PT; ++i) {
            unsigned k = k0[i];
            if ((k >> 12) == prefB)
                atomicAdd(&hist[k & 0xFFFu], 1u);
        }
    }
    __syncthreads();                                           // S9

    unsigned b3;
    {
        unsigned ct = 0;
        {
            const uint4* hv = reinterpret_cast<const uint4*>(hist) + tid * 4;
#pragma unroll
            for (int q = 0; q < 4; ++q) {
                uint4 c = hv[q];
                ct += c.x + c.y + c.z + c.w;
            }
        }
        unsigned s = ct;
#pragma unroll
        for (int o = 1; o < 32; o <<= 1) {
            unsigned v = __shfl_down_sync(0xffffffffu, s, o);
            if (lane + o < 32) s += v;
        }
        if (lane == 0) wsum[warp] = s;
        __syncthreads();                                       // S10
        unsigned addh = 0;
#pragma unroll
        for (int w = 0; w < NW; ++w) if (w > warp) addh += wsum[w];
        unsigned beyond = (s - ct) + addh;
        if (beyond < kth && beyond + ct >= kth) {
            unsigned rb = beyond;
            for (int j = 15; j >= 0; --j) {
                unsigned c = hist[tid * 16 + j];
                if (rb < kth && rb + c >= kth) { selb = (unsigned)(tid * 16 + j); selk = kth - rb; }
                rb += c;
            }
        }
        __syncthreads();                                       // S11
        b3  = selb;
        kth = selk;
        __syncthreads();   // all reads of selb/selk + wsum done // S12
    }

    const unsigned T    = (b1 << 24) | (b2 << 12) | b3;  // exact K-th largest key
    const unsigned need = kth;                           // # of ==T kept (lowest index)

    // ---------------- stable rank among ==T elements ----------------
    unsigned ceq = 0;
#pragma unroll
    for (int i = 0; i < PT; ++i) ceq += (k0[i] == T) ? 1u : 0u;
    unsigned p = ceq;
#pragma unroll
    for (int o = 1; o < 32; o <<= 1) {
        unsigned v = __shfl_up_sync(0xffffffffu, p, o);
        if (lane >= o) p += v;
    }
    if (lane == 31) wsum[warp] = p;
    __syncthreads();                                           // S13
    unsigned woff = 0;
#pragma unroll
    for (int w = 0; w < NW; ++w) if (w < warp) woff += wsum[w];
    unsigned rank = woff + p - ceq;   // exclusive prefix of equals, index order

    // ---------------- emit ----------------
    float4* outr = reinterpret_cast<float4*>(out + row) + tid * 4;
#pragma unroll
    for (int j = 0; j < 4; ++j) {
        float r[4];
#pragma unroll
        for (int c = 0; c < 4; ++c) {
            unsigned k = k0[j * 4 + c];
            bool eq = (k == T);
            bool keep = (k > T) || (eq && (rank < need));
            r[c] = keep ? k2f(k) : 0.0f;
            rank += eq ? 1u : 0u;
        }
        outr[j] = make_float4(r[0], r[1], r[2], r[3]);
    }
}

extern "C" void kernel_launch(void* const* d_in, const int* in_sizes, int n_in,
                              void* d_out, int out_size) {
    const float* x = (const float*)d_in[0];
    float* out = (float*)d_out;
    int rows = out_size / D_DIM;   // 16384
    topk_keep_kernel<<<rows, NT>>>(x, out);
}

// round 6
// speedup vs baseline: 1.7132x; 1.6307x over previous
#include <cuda_runtime.h>
#include <cstdint>

// TopK keep: zero all but the K=512 largest entries per 4096-wide row.
// One CTA (256 thr) per row, 16 keys/thread register-resident.
//
// Candidate-filtered radix select: only elements with key >= f2k(0.875)
// (bin-aligned) enter the histograms (~780 of 4096 for N(0,1) rows).
// Levels: 12-bit (2048 bins, offset 0x800) -> 10-bit -> 10-bit.
// If a row has fewer than K candidates (never for this input), an exact
// ballot binary search fallback runs. Ties: lowest index first, exact.

#define D_DIM   4096
#define K_KEEP  512
#define NT      256
#define PT      16
#define NW      8
#define T0K     0xBF600000u   // f2k(0.875f), 2^20-aligned

__device__ __forceinline__ unsigned f2k(float f) {
    unsigned u = __float_as_uint(f);
    return u ^ ((unsigned)((int)u >> 31) | 0x80000000u);
}
__device__ __forceinline__ float k2f(unsigned k) {
    return __uint_as_float(k ^ ((unsigned)((int)(~k) >> 31) | 0x80000000u));
}

// stable rank among ==T (global index order) + masked write-out
__device__ __forceinline__ void rank_emit(const unsigned* k0, unsigned T, unsigned need,
                                          float* __restrict__ out, size_t row,
                                          int tid, int lane, int warp, unsigned* wsum)
{
    __syncthreads();   // protect wsum reuse
    unsigned ceq = 0;
#pragma unroll
    for (int i = 0; i < PT; ++i) ceq += (k0[i] == T) ? 1u : 0u;
    unsigned p = ceq;
#pragma unroll
    for (int o = 1; o < 32; o <<= 1) {
        unsigned v = __shfl_up_sync(0xffffffffu, p, o);
        if (lane >= o) p += v;
    }
    if (lane == 31) wsum[warp] = p;
    __syncthreads();
    unsigned woff = 0;
#pragma unroll
    for (int w = 0; w < NW; ++w) if (w < warp) woff += wsum[w];
    unsigned rank = woff + p - ceq;

    float4* outr = reinterpret_cast<float4*>(out + row) + tid * 4;
#pragma unroll
    for (int j = 0; j < 4; ++j) {
        float r[4];
#pragma unroll
        for (int c = 0; c < 4; ++c) {
            unsigned k = k0[j * 4 + c];
            bool eq = (k == T);
            bool keep = (k > T) || (eq && (rank < need));
            r[c] = keep ? k2f(k) : 0.0f;
            rank += eq ? 1u : 0u;
        }
        outr[j] = make_float4(r[0], r[1], r[2], r[3]);
    }
}

__global__ __launch_bounds__(NT, 6)
void topk_keep_kernel(const float* __restrict__ x, float* __restrict__ out)
{
    __shared__ __align__(16) unsigned hist1[2048];  // 8KB
    __shared__ __align__(16) unsigned hist2[1024];  // 4KB
    __shared__ __align__(16) unsigned hist3[1024];  // 4KB
    __shared__ unsigned wsum[NW];
    __shared__ unsigned selb, selk, stot;

    const int tid  = threadIdx.x;
    const int lane = tid & 31;
    const int warp = tid >> 5;
    const size_t row = (size_t)blockIdx.x * D_DIM;

    // ---- load + convert ----
    const float4* xr = reinterpret_cast<const float4*>(x + row) + tid * 4;
    unsigned k0[PT];
    {
        float4 v0 = xr[0], v1 = xr[1], v2 = xr[2], v3 = xr[3];
        k0[0]=f2k(v0.x);  k0[1]=f2k(v0.y);  k0[2]=f2k(v0.z);  k0[3]=f2k(v0.w);
        k0[4]=f2k(v1.x);  k0[5]=f2k(v1.y);  k0[6]=f2k(v1.z);  k0[7]=f2k(v1.w);
        k0[8]=f2k(v2.x);  k0[9]=f2k(v2.y);  k0[10]=f2k(v2.z); k0[11]=f2k(v2.w);
        k0[12]=f2k(v3.x); k0[13]=f2k(v3.y); k0[14]=f2k(v3.z); k0[15]=f2k(v3.w);
    }

    // ---- zero hists (16KB total, 4 uint4/thread) ----
    {
        const uint4 z4 = make_uint4(0u,0u,0u,0u);
        reinterpret_cast<uint4*>(hist1)[tid]       = z4;
        reinterpret_cast<uint4*>(hist1)[tid + 256] = z4;
        reinterpret_cast<uint4*>(hist2)[tid]       = z4;
        reinterpret_cast<uint4*>(hist3)[tid]       = z4;
    }
    __syncthreads();                                           // S1

    // ---- L1: 12-bit bins, candidates only ----
#pragma unroll
    for (int i = 0; i < PT; ++i) {
        unsigned k = k0[i];
        if (k >= T0K)
            atomicAdd(&hist1[(k >> 20) & 0x7FFu], 1u);
    }
    __syncthreads();                                           // S2

    unsigned kth = K_KEEP;
    unsigned tot;
    {
        const uint4* hv = reinterpret_cast<const uint4*>(hist1) + tid * 2;
        uint4 a = hv[0], b = hv[1];
        unsigned ct = a.x+a.y+a.z+a.w + b.x+b.y+b.z+b.w;
        unsigned s = ct;                          // in-warp suffix scan
#pragma unroll
        for (int o = 1; o < 32; o <<= 1) {
            unsigned v = __shfl_down_sync(0xffffffffu, s, o);
            if (lane + o < 32) s += v;
        }
        if (lane == 0) wsum[warp] = s;
        __syncthreads();                                       // S3
        unsigned addh = 0; tot = 0;
#pragma unroll
        for (int w = 0; w < NW; ++w) {
            unsigned v = wsum[w];
            tot += v;
            if (w > warp) addh += v;
        }
        if (tot >= K_KEEP) {
            unsigned beyond = (s - ct) + addh;
            if (beyond < kth && beyond + ct >= kth) {
                unsigned rb = beyond;
                for (int j = 7; j >= 0; --j) {
                    unsigned c = hist1[tid * 8 + j];
                    if (rb < kth && rb + c >= kth) { selb = (unsigned)(tid * 8 + j); selk = kth - rb; }
                    rb += c;
                }
            }
        }
        __syncthreads();                                       // S4
    }

    if (tot < K_KEEP) {
        // ---- exact fallback: 32-step ballot binary search (uniform branch) ----
        unsigned lo = 0u, hi = 0xFFFFFFFFu;
#pragma unroll 1
        while (lo < hi) {
            unsigned mid = lo + ((hi - lo) >> 1) + ((hi - lo) & 1u);
            unsigned c = 0;
#pragma unroll
            for (int i = 0; i < PT; ++i) c += (k0[i] >= mid) ? 1u : 0u;
#pragma unroll
            for (int o = 16; o > 0; o >>= 1) c += __shfl_down_sync(0xffffffffu, c, o);
            if (lane == 0) wsum[warp] = c;
            __syncthreads();
            if (warp == 0) {
                unsigned v = (lane < NW) ? wsum[lane] : 0u;
#pragma unroll
                for (int o = 4; o > 0; o >>= 1) v += __shfl_down_sync(0xffffffffu, v, o);
                if (lane == 0) stot = v;
            }
            __syncthreads();
            if (stot >= K_KEEP) lo = mid; else hi = mid - 1u;
        }
        const unsigned T = lo;
        unsigned cg = 0;
#pragma unroll
        for (int i = 0; i < PT; ++i) cg += (k0[i] > T) ? 1u : 0u;
#pragma unroll
        for (int o = 16; o > 0; o >>= 1) cg += __shfl_down_sync(0xffffffffu, cg, o);
        if (lane == 0) wsum[warp] = cg;
        __syncthreads();
        if (warp == 0) {
            unsigned v = (lane < NW) ? wsum[lane] : 0u;
#pragma unroll
            for (int o = 4; o > 0; o >>= 1) v += __shfl_down_sync(0xffffffffu, v, o);
            if (lane == 0) stot = v;
        }
        __syncthreads();
        rank_emit(k0, T, K_KEEP - stot, out, row, tid, lane, warp, wsum);
        return;
    }

    const unsigned b1full = 0x800u | selb;   // key>>20 of winning bin
    kth = selk;

    // ---- L2: next 10 bits ----
#pragma unroll
    for (int i = 0; i < PT; ++i) {
        unsigned k = k0[i];
        if ((k >> 20) == b1full)
            atomicAdd(&hist2[(k >> 10) & 0x3FFu], 1u);
    }
    __syncthreads();                                           // S5

    unsigned b2;
    {
        uint4 a = reinterpret_cast<const uint4*>(hist2)[tid];
        unsigned ct = a.x + a.y + a.z + a.w;
        unsigned s = ct;
#pragma unroll
        for (int o = 1; o < 32; o <<= 1) {
            unsigned v = __shfl_down_sync(0xffffffffu, s, o);
            if (lane + o < 32) s += v;
        }
        if (lane == 0) wsum[warp] = s;
        __syncthreads();                                       // S6
        unsigned addh = 0;
#pragma unroll
        for (int w = 0; w < NW; ++w) if (w > warp) addh += wsum[w];
        unsigned beyond = (s - ct) + addh;
        if (beyond < kth && beyond + ct >= kth) {
            unsigned rb = beyond;
            for (int j = 3; j >= 0; --j) {
                unsigned c = hist2[tid * 4 + j];
                if (rb < kth && rb + c >= kth) { selb = (unsigned)(tid * 4 + j); selk = kth - rb; }
                rb += c;
            }
        }
        __syncthreads();                                       // S7
        b2  = selb;
        kth = selk;
    }

    // ---- L3: last 10 bits ----
    {
        const unsigned pref = (b1full << 10) | b2;
#pragma unroll
        for (int i = 0; i < PT; ++i) {
            unsigned k = k0[i];
            if ((k >> 10) == pref)
                atomicAdd(&hist3[k & 0x3FFu], 1u);
        }
    }
    __syncthreads();                                           // S8

    unsigned b3;
    {
        uint4 a = reinterpret_cast<const uint4*>(hist3)[tid];
        unsigned ct = a.x + a.y + a.z + a.w;
        unsigned s = ct;
#pragma unroll
        for (int o = 1; o < 32; o <<= 1) {
            unsigned v = __shfl_down_sync(0xffffffffu, s, o);
            if (lane + o < 32) s += v;
        }
        if (lane == 0) wsum[warp] = s;
        __syncthreads();                                       // S9
        unsigned addh = 0;
#pragma unroll
        for (int w = 0; w < NW; ++w) if (w > warp) addh += wsum[w];
        unsigned beyond = (s - ct) + addh;
        if (beyond < kth && beyond + ct >= kth) {
            unsigned rb = beyond;
            for (int j = 3; j >= 0; --j) {
                unsigned c = hist3[tid * 4 + j];
                if (rb < kth && rb + c >= kth) { selb = (unsigned)(tid * 4 + j); selk = kth - rb; }
                rb += c;
            }
        }
        __syncthreads();                                       // S10
        b3  = selb;
        kth = selk;
    }

    const unsigned T = (b1full << 20) | (b2 << 10) | b3;  // exact K-th largest key
    rank_emit(k0, T, kth, out, row, tid, lane, warp, wsum);
}

extern "C" void kernel_launch(void* const* d_in, const int* in_sizes, int n_in,
                              void* d_out, int out_size) {
    const float* x = (const float*)d_in[0];
    float* out = (float*)d_out;
    int rows = out_size / D_DIM;   // 16384
    topk_keep_kernel<<<rows, NT>>>(x, out);
}

// round 7
// speedup vs baseline: 1.9576x; 1.1427x over previous
#include <cuda_runtime.h>
#include <cstdint>

// TopK keep: zero all but the K=512 largest entries per 4096-wide row.
// One CTA (256 thr) per row, 16 floats/thread register-resident.
//
// Candidate-filtered radix select on RAW FLOAT BITS (all candidates are
// positive, where IEEE order == unsigned bit order): only x >= 0.875f
// (~780/4096 for N(0,1)) enter the histograms.
// Levels: 11-bit eff (2048 bins = u>>20) -> 10-bit -> 10-bit (exact key).
// L3 winning-bin count == n_eq(T): when need == n_eq (always, for
// continuous data) the emit is a single float compare; the stable-rank
// tie path and an exact binary-search fallback (rows with < K candidates)
// are kept behind uniform branches for exactness on any input.

#define D_DIM   4096
#define K_KEEP  512
#define NT      256
#define PT      16
#define NW      8
#define T0F     0.875f

__device__ __forceinline__ unsigned f2k(float f) {
    unsigned u = __float_as_uint(f);
    return u ^ ((unsigned)((int)u >> 31) | 0x80000000u);
}
__device__ __forceinline__ float k2f(unsigned k) {
    return __uint_as_float(k ^ ((unsigned)((int)(~k) >> 31) | 0x80000000u));
}

__global__ __launch_bounds__(NT, 6)
void topk_keep_kernel(const float* __restrict__ x, float* __restrict__ out)
{
    __shared__ __align__(16) unsigned hist1[2048];  // 8KB
    __shared__ __align__(16) unsigned hist2[1024];  // 4KB
    __shared__ __align__(16) unsigned hist3[1024];  // 4KB
    __shared__ unsigned wsum[NW];
    __shared__ unsigned selb, selk, seln, stot;

    const int tid  = threadIdx.x;
    const int lane = tid & 31;
    const int warp = tid >> 5;
    const size_t row = (size_t)blockIdx.x * D_DIM;

    // ---- load: 16 floats in registers ----
    const float4* xr = reinterpret_cast<const float4*>(x + row) + tid * 4;
    float f0[PT];
    {
        float4 v0 = xr[0], v1 = xr[1], v2 = xr[2], v3 = xr[3];
        f0[0]=v0.x;  f0[1]=v0.y;  f0[2]=v0.z;  f0[3]=v0.w;
        f0[4]=v1.x;  f0[5]=v1.y;  f0[6]=v1.z;  f0[7]=v1.w;
        f0[8]=v2.x;  f0[9]=v2.y;  f0[10]=v2.z; f0[11]=v2.w;
        f0[12]=v3.x; f0[13]=v3.y; f0[14]=v3.z; f0[15]=v3.w;
    }

    // ---- zero hists (16KB) ----
    {
        const uint4 z4 = make_uint4(0u,0u,0u,0u);
        reinterpret_cast<uint4*>(hist1)[tid]       = z4;
        reinterpret_cast<uint4*>(hist1)[tid + 256] = z4;
        reinterpret_cast<uint4*>(hist2)[tid]       = z4;
        reinterpret_cast<uint4*>(hist3)[tid]       = z4;
    }
    __syncthreads();                                           // S1

    // ---- L1: bins = u >> 20 (candidates are positive: u>>20 <= 0x7F7) ----
#pragma unroll
    for (int i = 0; i < PT; ++i) {
        if (f0[i] >= T0F)
            atomicAdd(&hist1[__float_as_uint(f0[i]) >> 20], 1u);
    }
    __syncthreads();                                           // S2

    unsigned kth = K_KEEP;
    unsigned tot;
    {
        const uint4* hv = reinterpret_cast<const uint4*>(hist1) + tid * 2;
        uint4 a = hv[0], b = hv[1];
        unsigned ct = a.x+a.y+a.z+a.w + b.x+b.y+b.z+b.w;
        unsigned s = ct;                          // in-warp suffix scan
#pragma unroll
        for (int o = 1; o < 32; o <<= 1) {
            unsigned v = __shfl_down_sync(0xffffffffu, s, o);
            if (lane + o < 32) s += v;
        }
        if (lane == 0) wsum[warp] = s;
        __syncthreads();                                       // S3
        unsigned addh = 0; tot = 0;
#pragma unroll
        for (int w = 0; w < NW; ++w) {
            unsigned v = wsum[w];
            tot += v;
            if (w > warp) addh += v;
        }
        if (tot >= K_KEEP) {
            unsigned beyond = (s - ct) + addh;
            if (beyond < kth && beyond + ct >= kth) {
                unsigned rb = beyond;
                for (int j = 7; j >= 0; --j) {
                    unsigned c = hist1[tid * 8 + j];
                    if (rb < kth && rb + c >= kth) { selb = (unsigned)(tid * 8 + j); selk = kth - rb; }
                    rb += c;
                }
            }
        }
        __syncthreads();                                       // S4
    }

    if (tot < K_KEEP) {
        // ---- exact fallback: 32-step binary search in key space ----
        unsigned k0[PT];
#pragma unroll
        for (int i = 0; i < PT; ++i) k0[i] = f2k(f0[i]);
        unsigned lo = 0u, hi = 0xFFFFFFFFu;
#pragma unroll 1
        while (lo < hi) {
            unsigned mid = lo + ((hi - lo) >> 1) + ((hi - lo) & 1u);
            unsigned c = 0;
#pragma unroll
            for (int i = 0; i < PT; ++i) c += (k0[i] >= mid) ? 1u : 0u;
#pragma unroll
            for (int o = 16; o > 0; o >>= 1) c += __shfl_down_sync(0xffffffffu, c, o);
            if (lane == 0) wsum[warp] = c;
            __syncthreads();
            if (warp == 0) {
                unsigned v = (lane < NW) ? wsum[lane] : 0u;
#pragma unroll
                for (int o = 4; o > 0; o >>= 1) v += __shfl_down_sync(0xffffffffu, v, o);
                if (lane == 0) stot = v;
            }
            __syncthreads();
            if (stot >= K_KEEP) lo = mid; else hi = mid - 1u;
        }
        const unsigned T = lo;
        unsigned cg = 0, ceq = 0;
#pragma unroll
        for (int i = 0; i < PT; ++i) {
            cg  += (k0[i] > T)  ? 1u : 0u;
            ceq += (k0[i] == T) ? 1u : 0u;
        }
        {
            unsigned c = cg;
#pragma unroll
            for (int o = 16; o > 0; o >>= 1) c += __shfl_down_sync(0xffffffffu, c, o);
            if (lane == 0) wsum[warp] = c;
            __syncthreads();
            if (warp == 0) {
                unsigned v = (lane < NW) ? wsum[lane] : 0u;
#pragma unroll
                for (int o = 4; o > 0; o >>= 1) v += __shfl_down_sync(0xffffffffu, v, o);
                if (lane == 0) stot = v;
            }
            __syncthreads();
        }
        const unsigned need = K_KEEP - stot;
        __syncthreads();
        unsigned p = ceq;
#pragma unroll
        for (int o = 1; o < 32; o <<= 1) {
            unsigned v = __shfl_up_sync(0xffffffffu, p, o);
            if (lane >= o) p += v;
        }
        if (lane == 31) wsum[warp] = p;
        __syncthreads();
        unsigned woff = 0;
#pragma unroll
        for (int w = 0; w < NW; ++w) if (w < warp) woff += wsum[w];
        unsigned rank = woff + p - ceq;
        float4* outr = reinterpret_cast<float4*>(out + row) + tid * 4;
#pragma unroll
        for (int j = 0; j < 4; ++j) {
            float r[4];
#pragma unroll
            for (int c2 = 0; c2 < 4; ++c2) {
                unsigned k = k0[j * 4 + c2];
                bool eq = (k == T);
                bool keep = (k > T) || (eq && (rank < need));
                r[c2] = keep ? k2f(k) : 0.0f;
                rank += eq ? 1u : 0u;
            }
            outr[j] = make_float4(r[0], r[1], r[2], r[3]);
        }
        return;
    }

    const unsigned b1 = selb;
    kth = selk;

    // ---- L2: next 10 bits ----
#pragma unroll
    for (int i = 0; i < PT; ++i) {
        unsigned u = __float_as_uint(f0[i]);
        if ((u >> 20) == b1)
            atomicAdd(&hist2[(u >> 10) & 0x3FFu], 1u);
    }
    __syncthreads();                                           // S5

    unsigned b2;
    {
        uint4 a = reinterpret_cast<const uint4*>(hist2)[tid];
        unsigned ct = a.x + a.y + a.z + a.w;
        unsigned s = ct;
#pragma unroll
        for (int o = 1; o < 32; o <<= 1) {
            unsigned v = __shfl_down_sync(0xffffffffu, s, o);
            if (lane + o < 32) s += v;
        }
        if (lane == 0) wsum[warp] = s;
        __syncthreads();                                       // S6
        unsigned addh = 0;
#pragma unroll
        for (int w = 0; w < NW; ++w) if (w > warp) addh += wsum[w];
        unsigned beyond = (s - ct) + addh;
        if (beyond < kth && beyond + ct >= kth) {
            unsigned rb = beyond;
            for (int j = 3; j >= 0; --j) {
                unsigned c = hist2[tid * 4 + j];
                if (rb < kth && rb + c >= kth) { selb = (unsigned)(tid * 4 + j); selk = kth - rb; }
                rb += c;
            }
        }
        __syncthreads();                                       // S7
        b2  = selb;
        kth = selk;
    }

    // ---- L3: last 10 bits (bin == exact key) ----
    const unsigned pref = (b1 << 10) | b2;
#pragma unroll
    for (int i = 0; i < PT; ++i) {
        unsigned u = __float_as_uint(f0[i]);
        if ((u >> 10) == pref)
            atomicAdd(&hist3[u & 0x3FFu], 1u);
    }
    __syncthreads();                                           // S8

    {
        uint4 a = reinterpret_cast<const uint4*>(hist3)[tid];
        unsigned ct = a.x + a.y + a.z + a.w;
        unsigned s = ct;
#pragma unroll
        for (int o = 1; o < 32; o <<= 1) {
            unsigned v = __shfl_down_sync(0xffffffffu, s, o);
            if (lane + o < 32) s += v;
        }
        if (lane == 0) wsum[warp] = s;
        __syncthreads();                                       // S9
        unsigned addh = 0;
#pragma unroll
        for (int w = 0; w < NW; ++w) if (w > warp) addh += wsum[w];
        unsigned beyond = (s - ct) + addh;
        if (beyond < kth && beyond + ct >= kth) {
            unsigned rb = beyond;
            for (int j = 3; j >= 0; --j) {
                unsigned c = hist3[tid * 4 + j];
                if (rb < kth && rb + c >= kth) {
                    selb = (unsigned)(tid * 4 + j);
                    selk = kth - rb;
                    seln = c;              // n_eq(T): bin == exact key
                }
                rb += c;
            }
        }
        __syncthreads();                                       // S10
    }

    const unsigned T    = (pref << 10) | selb;   // exact K-th largest key (raw bits)
    const unsigned need = selk;                  // # of ==T to keep
    const unsigned neq  = seln;                  // # of ==T present
    const float    Tf   = __uint_as_float(T);    // positive float

    if (need == neq) {
        // ---- fast emit: keep everything >= Tf (all ties kept) ----
        float4* outr = reinterpret_cast<float4*>(out + row) + tid * 4;
#pragma unroll
        for (int j = 0; j < 4; ++j) {
            float4 o;
            o.x = (f0[j*4+0] >= Tf) ? f0[j*4+0] : 0.0f;
            o.y = (f0[j*4+1] >= Tf) ? f0[j*4+1] : 0.0f;
            o.z = (f0[j*4+2] >= Tf) ? f0[j*4+2] : 0.0f;
            o.w = (f0[j*4+3] >= Tf) ? f0[j*4+3] : 0.0f;
            outr[j] = o;
        }
        return;
    }

    // ---- rare tie path: stable rank, lowest index first ----
    __syncthreads();   // wsum reuse
    unsigned ceq = 0;
#pragma unroll
    for (int i = 0; i < PT; ++i) ceq += (f0[i] == Tf) ? 1u : 0u;
    unsigned p = ceq;
#pragma unroll
    for (int o = 1; o < 32; o <<= 1) {
        unsigned v = __shfl_up_sync(0xffffffffu, p, o);
        if (lane >= o) p += v;
    }
    if (lane == 31) wsum[warp] = p;
    __syncthreads();
    unsigned woff = 0;
#pragma unroll
    for (int w = 0; w < NW; ++w) if (w < warp) woff += wsum[w];
    unsigned rank = woff + p - ceq;

    float4* outr = reinterpret_cast<float4*>(out + row) + tid * 4;
#pragma unroll
    for (int j = 0; j < 4; ++j) {
        float r[4];
#pragma unroll
        for (int c = 0; c < 4; ++c) {
            float f = f0[j * 4 + c];
            bool eq = (f == Tf);
            bool keep = (f > Tf) || (eq && (rank < need));
            r[c] = keep ? f : 0.0f;
            rank += eq ? 1u : 0u;
        }
        outr[j] = make_float4(r[0], r[1], r[2], r[3]);
    }
}

extern "C" void kernel_launch(void* const* d_in, const int* in_sizes, int n_in,
                              void* d_out, int out_size) {
    const float* x = (const float*)d_in[0];
    float* out = (float*)d_out;
    int rows = out_size / D_DIM;   // 16384
    topk_keep_kernel<<<rows, NT>>>(x, out);
}